// round 3
// baseline (speedup 1.0000x reference)
#include <cuda_runtime.h>

#define NUM_C 8192
#define NUM_B 256
#define SPLIT 4
#define CHUNK (NUM_C / SPLIT)       // 2048
#define NT    256
#define NWARP (NT / 32)
#define EPSF  1e-6f

// cross-block accumulators (allocation-free rule: __device__ globals; all are
// reset in-kernel after use so every graph replay starts from a clean state)
__device__ float        g_denom[NUM_B];
__device__ unsigned int g_row_cnt[NUM_B];
__device__ float        g_sum   = 0.0f;
__device__ unsigned int g_cnt   = 0u;

__global__ __launch_bounds__(NT)
void seesaw_split_kernel(const float* __restrict__ logits,
                         const float* __restrict__ targets,
                         const float* __restrict__ s,
                         float* __restrict__ out)
{
    __shared__ float sh_warp[NWARP];
    __shared__ int   sh_label;

    const int chunk = blockIdx.x;          // 0..SPLIT-1
    const int b     = blockIdx.y;          // row
    const int tid   = threadIdx.x;
    const int lane  = tid & 31;
    const int wid   = tid >> 5;

    // ---- phase 1: full-row targets scan for the one-hot label ----
    // (siblings of the same row read the same bytes -> L2 hits; DRAM sees it once)
    const int4* tg4 = (const int4*)(targets + (size_t)b * NUM_C);
    #pragma unroll
    for (int i = 0; i < NUM_C / 4 / NT; i++) {         // 8 iters
        int idx4 = tid + i * NT;
        int4 t = tg4[idx4];                            // one-hot: nonzero bits == 1.0f
        if (t.x | t.y | t.z | t.w) {
            int j = idx4 * 4;
            if (t.x) sh_label = j + 0;
            if (t.y) sh_label = j + 1;
            if (t.z) sh_label = j + 2;
            if (t.w) sh_label = j + 3;
        }
    }
    __syncthreads();
    const int lab = sh_label;

    // ---- phase 2: partial dot over this block's 2048-class chunk ----
    // denom_b = sum_j s[lab,j] * exp(logits[b,j])   (s diag==1 folds the +expl term;
    // max-shift dropped: it only rescales +eps by e^{-max}, ~1e-8 effect on sigma)
    const float4* lg4 = (const float4*)(logits + (size_t)b * NUM_C + (size_t)chunk * CHUNK);
    const float4* s4  = (const float4*)(s + (size_t)lab * NUM_C + (size_t)chunk * CHUNK);
    float acc = 0.f;
    #pragma unroll
    for (int i = 0; i < CHUNK / 4 / NT; i++) {         // 2 iters
        int idx4 = tid + i * NT;
        float4 v  = lg4[idx4];
        float4 sv = s4[idx4];
        acc += sv.x * __expf(v.x) + sv.y * __expf(v.y)
             + sv.z * __expf(v.z) + sv.w * __expf(v.w);
    }

    // block reduce
    #pragma unroll
    for (int off = 16; off > 0; off >>= 1)
        acc += __shfl_down_sync(0xffffffffu, acc, off);
    if (lane == 0) sh_warp[wid] = acc;
    __syncthreads();

    if (wid == 0 && lane == 0) {
        float blk = sh_warp[0];
        #pragma unroll
        for (int w = 1; w < NWARP; w++) blk += sh_warp[w];

        atomicAdd(&g_denom[b], blk);
        __threadfence();
        unsigned int tkt = atomicAdd(&g_row_cnt[b], 1u);
        if (tkt == SPLIT - 1u) {
            // all partials for row b are in; drain + reset for next replay
            float denom = atomicExch(&g_denom[b], 0.0f);
            g_row_cnt[b] = 0u;
            float elab  = __expf(__ldg(logits + (size_t)b * NUM_C + lab));
            float sigma = elab / (denom + EPSF);
            float loss  = -logf(sigma + EPSF);

            atomicAdd(&g_sum, loss);
            __threadfence();
            unsigned int t2 = atomicAdd(&g_cnt, 1u);
            if (t2 == NUM_B - 1u) {
                float total = atomicExch(&g_sum, 0.0f);
                g_cnt = 0u;
                out[0] = total * (1.0f / NUM_B);
            }
        }
    }
}

extern "C" void kernel_launch(void* const* d_in, const int* in_sizes, int n_in,
                              void* d_out, int out_size)
{
    const float* logits  = (const float*)d_in[0];
    const float* targets = (const float*)d_in[1];
    const float* s       = (const float*)d_in[2];
    float* out = (float*)d_out;

    dim3 grid(SPLIT, NUM_B);
    seesaw_split_kernel<<<grid, NT>>>(logits, targets, s, out);
}

// round 4
// speedup vs baseline: 1.0119x; 1.0119x over previous
#include <cuda_runtime.h>

#define NUM_C 8192
#define NUM_B 256
#define SPLIT 4
#define CHUNK (NUM_C / SPLIT)       // 2048
#define NT    256
#define NWARP (NT / 32)
#define EPSF  1e-6f

// cross-block state (allocation-free rule: __device__ globals; everything is
// reset in-kernel after its row/grid completes, so graph replays start clean)
__device__ unsigned int g_label[NUM_B];     // 0 = unknown, else label+1
__device__ float        g_denom[NUM_B];
__device__ unsigned int g_row_cnt[NUM_B];
__device__ float        g_sum = 0.0f;
__device__ unsigned int g_cnt = 0u;

__global__ __launch_bounds__(NT, 8)
void seesaw_split2_kernel(const float* __restrict__ logits,
                          const float* __restrict__ targets,
                          const float* __restrict__ s,
                          float* __restrict__ out)
{
    __shared__ float sh_e[CHUNK];           // 8 KB: exp(logits) for this chunk
    __shared__ float sh_warp[NWARP];
    __shared__ int   sh_label;              // -1 until known

    const int chunk = blockIdx.x;           // 0..SPLIT-1
    const int b     = blockIdx.y;           // row
    const int tid   = threadIdx.x;
    const int lane  = tid & 31;
    const int wid   = tid >> 5;

    if (tid == 0) sh_label = -1;
    __syncthreads();

    const size_t rowoff = (size_t)b * NUM_C;
    const size_t coff   = rowoff + (size_t)chunk * CHUNK;

    // ---- phase A (label-independent): scan OWN targets chunk; exp own logits
    //      chunk into smem. The one sibling holding the one-hot publishes it. ----
    const int4*   tg4 = (const int4*)(targets + coff);
    const float4* lg4 = (const float4*)(logits + coff);
    float4* she4 = (float4*)sh_e;

    #pragma unroll
    for (int i = 0; i < CHUNK / 4 / NT; i++) {          // 2 iters
        int idx4 = tid + i * NT;
        int4   t = tg4[idx4];
        float4 v = lg4[idx4];
        float4 e;
        e.x = __expf(v.x); e.y = __expf(v.y);
        e.z = __expf(v.z); e.w = __expf(v.w);
        she4[idx4] = e;
        if (t.x | t.y | t.z | t.w) {
            int j = chunk * CHUNK + idx4 * 4;
            int l = t.x ? j : (t.y ? j + 1 : (t.z ? j + 2 : j + 3));
            sh_label = l;
            atomicExch(&g_label[b], (unsigned)l + 1u);   // publish to siblings
        }
    }
    __syncthreads();

    // ---- resolve label: local hit, else poll the publisher (bounded), else
    //      deadlock-proof fallback: scan the full (L2-hot) targets row. ----
    if (sh_label < 0) {
        if (tid == 0) {
            int l = -1;
            for (int it = 0; it < 50000; it++) {
                unsigned v = atomicAdd(&g_label[b], 0u);
                if (v) { l = (int)v - 1; break; }
                __nanosleep(60);
            }
            sh_label = l;
        }
        __syncthreads();
        if (sh_label < 0) {                               // fallback (never expected)
            const int4* trow = (const int4*)(targets + rowoff);
            for (int i = 0; i < NUM_C / 4 / NT; i++) {
                int idx4 = tid + i * NT;
                int4 t = trow[idx4];
                if (t.x | t.y | t.z | t.w) {
                    int j = idx4 * 4;
                    sh_label = t.x ? j : (t.y ? j + 1 : (t.z ? j + 2 : j + 3));
                }
            }
            __syncthreads();
        }
    }
    const int lab = sh_label;

    // ---- phase B: partial denom over this chunk:  sum_j s[lab,j]*e_j
    //      (s diag==1 folds in the +expl term; max-shift dropped: only rescales
    //       +eps by e^{-max}, ~1e-8 relative effect on sigma) ----
    const float4* s4 = (const float4*)(s + (size_t)lab * NUM_C + (size_t)chunk * CHUNK);
    float acc = 0.f;
    #pragma unroll
    for (int i = 0; i < CHUNK / 4 / NT; i++) {          // 2 iters
        int idx4 = tid + i * NT;
        float4 sv = s4[idx4];
        float4 e  = she4[idx4];
        acc += sv.x * e.x + sv.y * e.y + sv.z * e.z + sv.w * e.w;
    }

    #pragma unroll
    for (int off = 16; off > 0; off >>= 1)
        acc += __shfl_down_sync(0xffffffffu, acc, off);
    if (lane == 0) sh_warp[wid] = acc;
    __syncthreads();

    if (tid == 0) {
        float blk = sh_warp[0];
        #pragma unroll
        for (int w = 1; w < NWARP; w++) blk += sh_warp[w];

        atomicAdd(&g_denom[b], blk);
        __threadfence();
        unsigned int tkt = atomicAdd(&g_row_cnt[b], 1u);
        if (tkt == SPLIT - 1u) {
            // row complete: drain + reset row state for the next graph replay
            float denom = atomicExch(&g_denom[b], 0.0f);
            g_row_cnt[b] = 0u;
            g_label[b]   = 0u;           // safe: all siblings already consumed it
            float elab  = __expf(__ldg(logits + rowoff + lab));
            float sigma = elab / (denom + EPSF);
            float loss  = -logf(sigma + EPSF);

            atomicAdd(&g_sum, loss);
            __threadfence();
            unsigned int t2 = atomicAdd(&g_cnt, 1u);
            if (t2 == NUM_B - 1u) {
                float total = atomicExch(&g_sum, 0.0f);
                g_cnt = 0u;
                out[0] = total * (1.0f / NUM_B);
            }
        }
    }
}

extern "C" void kernel_launch(void* const* d_in, const int* in_sizes, int n_in,
                              void* d_out, int out_size)
{
    const float* logits  = (const float*)d_in[0];
    const float* targets = (const float*)d_in[1];
    const float* s       = (const float*)d_in[2];
    float* out = (float*)d_out;

    dim3 grid(SPLIT, NUM_B);
    seesaw_split2_kernel<<<grid, NT>>>(logits, targets, s, out);
}

// round 5
// speedup vs baseline: 1.3178x; 1.3023x over previous
#include <cuda_runtime.h>

#define NUM_C 8192
#define NUM_B 256
#define NT    512
#define NWARP (NT / 32)
#define EPSF  1e-6f

// cross-block accumulators (allocation-free rule: __device__ globals; reset
// in-kernel after the grid completes so every graph replay starts clean)
__device__ float        g_sum = 0.0f;
__device__ unsigned int g_cnt = 0u;

__global__ __launch_bounds__(NT)
void seesaw_v5_kernel(const float* __restrict__ logits,
                      const float* __restrict__ targets,
                      const float* __restrict__ s,
                      float* __restrict__ out)
{
    __shared__ float sh_warp[NWARP];
    __shared__ int   sh_label;

    const int b    = blockIdx.x;
    const int tid  = threadIdx.x;
    const int lane = tid & 31;
    const int wid  = tid >> 5;

    const size_t rowoff = (size_t)b * NUM_C;

    // ---- phase T: targets-only scan (the sole label dependency). 4 batched
    //      int4 loads per thread -> high MLP, 32 KB per row total. ----
    {
        const int4* tg4 = (const int4*)(targets + rowoff);
        int4 t0 = tg4[tid + 0 * NT];
        int4 t1 = tg4[tid + 1 * NT];
        int4 t2 = tg4[tid + 2 * NT];
        int4 t3 = tg4[tid + 3 * NT];

        int l = -1;
        if (t0.x | t0.y | t0.z | t0.w) {
            int j = (tid + 0 * NT) * 4;
            l = t0.x ? j : (t0.y ? j + 1 : (t0.z ? j + 2 : j + 3));
        }
        if (t1.x | t1.y | t1.z | t1.w) {
            int j = (tid + 1 * NT) * 4;
            l = t1.x ? j : (t1.y ? j + 1 : (t1.z ? j + 2 : j + 3));
        }
        if (t2.x | t2.y | t2.z | t2.w) {
            int j = (tid + 2 * NT) * 4;
            l = t2.x ? j : (t2.y ? j + 1 : (t2.z ? j + 2 : j + 3));
        }
        if (t3.x | t3.y | t3.z | t3.w) {
            int j = (tid + 3 * NT) * 4;
            l = t3.x ? j : (t3.y ? j + 1 : (t3.z ? j + 2 : j + 3));
        }
        if (l >= 0) sh_label = l;       // exactly one thread writes
    }
    __syncthreads();
    const int lab = sh_label;

    // ---- phase S: denom = sum_j s[lab,j] * exp(logits[b,j]); 8 batched
    //      float4 loads per thread before any math -> MLP ~8/warp.
    //      (s diag==1 folds the +expl term; max-shift dropped: it only
    //       rescales +eps by e^{-max}, ~1e-8 relative effect on sigma) ----
    const float4* lg4 = (const float4*)(logits + rowoff);
    const float4* s4  = (const float4*)(s + (size_t)lab * NUM_C);

    float4 l0 = lg4[tid + 0 * NT];
    float4 l1 = lg4[tid + 1 * NT];
    float4 l2 = lg4[tid + 2 * NT];
    float4 l3 = lg4[tid + 3 * NT];
    float4 s0 = s4[tid + 0 * NT];
    float4 s1 = s4[tid + 1 * NT];
    float4 s2 = s4[tid + 2 * NT];
    float4 s3 = s4[tid + 3 * NT];

    float acc = 0.f;
    acc += s0.x * __expf(l0.x) + s0.y * __expf(l0.y)
         + s0.z * __expf(l0.z) + s0.w * __expf(l0.w);
    acc += s1.x * __expf(l1.x) + s1.y * __expf(l1.y)
         + s1.z * __expf(l1.z) + s1.w * __expf(l1.w);
    acc += s2.x * __expf(l2.x) + s2.y * __expf(l2.y)
         + s2.z * __expf(l2.z) + s2.w * __expf(l2.w);
    acc += s3.x * __expf(l3.x) + s3.y * __expf(l3.y)
         + s3.z * __expf(l3.z) + s3.w * __expf(l3.w);

    // ---- block reduce ----
    #pragma unroll
    for (int off = 16; off > 0; off >>= 1)
        acc += __shfl_down_sync(0xffffffffu, acc, off);
    if (lane == 0) sh_warp[wid] = acc;
    __syncthreads();

    if (wid == 0) {
        float v = (lane < NWARP) ? sh_warp[lane] : 0.f;
        #pragma unroll
        for (int off = 8; off > 0; off >>= 1)
            v += __shfl_down_sync(0xffffffffu, v, off);

        if (lane == 0) {
            float denom = v;
            float elab  = __expf(__ldg(logits + rowoff + lab));  // L2-hot
            float sigma = elab / (denom + EPSF);
            float loss  = -logf(sigma + EPSF);

            atomicAdd(&g_sum, loss);
            __threadfence();
            unsigned int tkt = atomicAdd(&g_cnt, 1u);
            if (tkt == NUM_B - 1u) {
                float total = atomicExch(&g_sum, 0.0f);   // drain + reset
                g_cnt = 0u;
                out[0] = total * (1.0f / NUM_B);
            }
        }
    }
}

extern "C" void kernel_launch(void* const* d_in, const int* in_sizes, int n_in,
                              void* d_out, int out_size)
{
    const float* logits  = (const float*)d_in[0];
    const float* targets = (const float*)d_in[1];
    const float* s       = (const float*)d_in[2];
    float* out = (float*)d_out;

    seesaw_v5_kernel<<<NUM_B, NT>>>(logits, targets, s, out);
}